// round 6
// baseline (speedup 1.0000x reference)
#include <cuda_runtime.h>

#define TT 2048
#define BB 4096
#define OUTLEN 25
#define WPD 410            // warps per direction (10 tasks each)
#define NWIN (TT/8)        // 256 windows of 8 steps

__device__ float g_y[BB * 18];

__device__ __forceinline__ float tanha(float x) {
    float y; asm("tanh.approx.f32 %0,%1;" : "=f"(y) : "f"(x)); return y;
}
__device__ __forceinline__ float ftanh(float x) {
    x = fminf(fmaxf(x, -9.0f), 9.0f);
    float e = __expf(2.0f * x);
    return __fdividef(e - 1.0f, e + 1.0f);
}

__global__ void dummy_kernel() {}

// ---------------------------------------------------------------------------
// Stage 1: bidirectional Elman RNN H1=9, T=2048. Split-3: one (batch,dir)
// task = 3 lanes, lane r owns units 3r..3r+2; 10 tasks/warp; 820 warps over
// 205 CTAs x 4 warps (full-chip spread).
// Per 8-step window: zx[q][m] = Wih.x_t + b precomputed in bulk (ILP, off
// the recurrent chain), then 8 recurrent steps whose chain is only
// shfl -> 3-FMA -> add-tree -> tanh.approx (~64 cy).
// x staged via coalesced LDG.128 -> per-warp smem, double buffered.
// tanh.approx everywhere except the last 32 steps (precise tail; contraction
// rho~0.33 measured in R0 wipes the approx error).
// ---------------------------------------------------------------------------
__global__ __launch_bounds__(128) void rnn1_kernel(
    const float* __restrict__ x,
    const float* __restrict__ wih_f, const float* __restrict__ whh_f,
    const float* __restrict__ bih_f, const float* __restrict__ bhh_f,
    const float* __restrict__ wih_b, const float* __restrict__ whh_b,
    const float* __restrict__ bih_b, const float* __restrict__ bhh_b)
{
    // [warp][buf][task*44 + step*5 + k] : 10 tasks x 40 floats, pad to 44
    __shared__ float sxf[4][2][440];

    const int wIn  = threadIdx.x >> 5;
    const int lane = threadIdx.x & 31;
    const int wid  = blockIdx.x * 4 + wIn;
    if (wid >= 2 * WPD) return;

    const bool bwd = (wid >= WPD);
    const int  wg  = bwd ? wid - WPD : wid;
    const int  tri = min(lane / 3, 9);    // lanes 30,31 shadow task 9
    const int  r   = lane % 3;
    const int  rA  = (r + 1) % 3, rB = (r + 2) % 3;
    const int  laneA = 3 * tri + rA, laneB = 3 * tri + rB;

    const float* wih = bwd ? wih_b : wih_f;
    const float* whh = bwd ? whh_b : whh_f;
    const float* bih = bwd ? bih_b : bih_f;
    const float* bhh = bwd ? bhh_b : bhh_f;

    // Weight rows for units j = 3r+m; Whh columns grouped [own][laneA][laneB]
    float Wi[3][5], WhO[3][3], WhA[3][3], WhB[3][3], Bv[3];
    #pragma unroll
    for (int m = 0; m < 3; m++) {
        const int j = 3 * r + m;
        #pragma unroll
        for (int k = 0; k < 5; k++) Wi[m][k] = wih[j * 5 + k];
        #pragma unroll
        for (int i = 0; i < 3; i++) {
            WhO[m][i] = whh[j * 9 + 3 * r  + i];
            WhA[m][i] = whh[j * 9 + 3 * rA + i];
            WhB[m][i] = whh[j * 9 + 3 * rB + i];
        }
        Bv[m] = bih[j] + bhh[j];
    }

    // ---- coalesced loader: 100 float4 chunks (task 0..9, chunk c 0..9) ----
    const char* xc = (const char*)x;
    size_t gaddr[4];
    int    soff4[4];
    #pragma unroll
    for (int k = 0; k < 4; k++) {
        int idx = min(lane + 32 * k, 99);
        int task = idx / 10, c = idx - 10 * task;
        int b = min(wg * 10 + task, BB - 1);
        gaddr[k] = (size_t)b * (TT * 20) + (size_t)c * 16;
        soff4[k] = task * 11 + c;
    }
    float4 pf[4];

    #define PFLOAD(g) do {                                                    \
        size_t wb = (size_t)(bwd ? (TT - 8 - 8 * (g)) : (8 * (g))) * 20;      \
        _Pragma("unroll")                                                     \
        for (int k = 0; k < 4; k++)                                           \
            if (lane + 32 * k < 100)                                          \
                pf[k] = *reinterpret_cast<const float4*>(xc + gaddr[k] + wb); \
    } while (0)

    #define STSW(buf) do {                                                    \
        float4* s4 = reinterpret_cast<float4*>(&sxf[wIn][buf][0]);            \
        _Pragma("unroll")                                                     \
        for (int k = 0; k < 4; k++)                                           \
            if (lane + 32 * k < 100) s4[soff4[k]] = pf[k];                    \
    } while (0)

    float h0 = 0.f, h1 = 0.f, h2 = 0.f;
    float Ha[3] = {0.f, 0.f, 0.f}, Hb[3] = {0.f, 0.f, 0.f};
    float zxw[8][3];

    // bulk zx precompute for a window (independent of h; full ILP)
    #define ZXW(buf) do {                                                     \
        const float* xw = &sxf[wIn][buf][tri * 44];                           \
        _Pragma("unroll")                                                     \
        for (int q = 0; q < 8; q++) {                                         \
            float x0 = xw[q*5+0], x1 = xw[q*5+1], x2 = xw[q*5+2];             \
            float x3 = xw[q*5+3], x4 = xw[q*5+4];                             \
            _Pragma("unroll")                                                 \
            for (int m = 0; m < 3; m++) {                                     \
                float z = Bv[m];                                              \
                z = fmaf(Wi[m][0], x0, z); z = fmaf(Wi[m][1], x1, z);         \
                z = fmaf(Wi[m][2], x2, z); z = fmaf(Wi[m][3], x3, z);         \
                z = fmaf(Wi[m][4], x4, z);                                    \
                zxw[q][m] = z;                                                \
            }                                                                 \
        }                                                                     \
    } while (0)

    #define STEP(TANHF, q) do {                                               \
        float nh0, nh1, nh2;                                                  \
        _Pragma("unroll")                                                     \
        for (int m = 0; m < 3; m++) {                                         \
            float zo = WhO[m][0] * h0;                                        \
            zo = fmaf(WhO[m][1], h1, zo); zo = fmaf(WhO[m][2], h2, zo);       \
            float za = WhA[m][0] * Ha[0];                                     \
            za = fmaf(WhA[m][1], Ha[1], za); za = fmaf(WhA[m][2], Ha[2], za); \
            float zb = WhB[m][0] * Hb[0];                                     \
            zb = fmaf(WhB[m][1], Hb[1], zb); zb = fmaf(WhB[m][2], Hb[2], zb); \
            float z = (zxw[q][m] + zo) + (za + zb);                           \
            float t_ = TANHF(z);                                              \
            if (m == 0) nh0 = t_; else if (m == 1) nh1 = t_; else nh2 = t_;   \
        }                                                                     \
        h0 = nh0; h1 = nh1; h2 = nh2;                                         \
        Ha[0] = __shfl_sync(0xffffffffu, h0, laneA);                          \
        Ha[1] = __shfl_sync(0xffffffffu, h1, laneA);                          \
        Ha[2] = __shfl_sync(0xffffffffu, h2, laneA);                          \
        Hb[0] = __shfl_sync(0xffffffffu, h0, laneB);                          \
        Hb[1] = __shfl_sync(0xffffffffu, h1, laneB);                          \
        Hb[2] = __shfl_sync(0xffffffffu, h2, laneB);                          \
    } while (0)

    #define CONS(TANHF) do {                                                  \
        if (!bwd) {                                                           \
            STEP(TANHF, 0); STEP(TANHF, 1); STEP(TANHF, 2); STEP(TANHF, 3);   \
            STEP(TANHF, 4); STEP(TANHF, 5); STEP(TANHF, 6); STEP(TANHF, 7);   \
        } else {                                                              \
            STEP(TANHF, 7); STEP(TANHF, 6); STEP(TANHF, 5); STEP(TANHF, 4);   \
            STEP(TANHF, 3); STEP(TANHF, 2); STEP(TANHF, 1); STEP(TANHF, 0);   \
        }                                                                     \
    } while (0)

    PFLOAD(0);
    STSW(0);
    PFLOAD(1);
    __syncwarp();
    for (int g = 0; g < NWIN; g++) {
        const int buf = g & 1;
        ZXW(buf);
        if (g < NWIN - 4) CONS(tanha);
        else              CONS(ftanh);
        if (g + 1 < NWIN) {
            STSW((g + 1) & 1);
            if (g + 2 < NWIN) PFLOAD(g + 2);
            __syncwarp();
        }
    }

    const int b = wg * 10 + tri;
    if (lane < 30 && b < BB) {
        float* dst = g_y + b * 18 + (bwd ? 9 : 0) + 3 * r;
        dst[0] = h0; dst[1] = h1; dst[2] = h2;
    }
    #undef PFLOAD
    #undef STSW
    #undef ZXW
    #undef STEP
    #undef CONS
}

// ---------------------------------------------------------------------------
// Stage 2: H2=32 RNN, 25 steps + linear 32->3 (R4 version, 27us).
// ---------------------------------------------------------------------------
__global__ __launch_bounds__(256) void rnn2_kernel(
    const float* __restrict__ wih2, const float* __restrict__ whh2,
    const float* __restrict__ bih2, const float* __restrict__ bhh2,
    const float* __restrict__ wout, const float* __restrict__ bout,
    float* __restrict__ out)
{
    __shared__ float swh[1024], swi[576], swo[96];
    __shared__ float hs[8][OUTLEN][32];

    const int tid = threadIdx.x;
    for (int i = tid; i < 1024; i += 256) swh[i] = whh2[i];
    for (int i = tid; i < 576;  i += 256) swi[i] = wih2[i];
    if (tid < 96) swo[tid] = wout[tid];
    __syncthreads();

    const int wIn = tid >> 5;
    const int j   = tid & 31;
    const int b   = blockIdx.x * 8 + wIn;

    float Wh[32];
    {
        const float4* p = reinterpret_cast<const float4*>(&swh[j * 32]);
        #pragma unroll
        for (int c = 0; c < 8; c++) {
            float4 v = p[c];
            Wh[4*c] = v.x; Wh[4*c+1] = v.y; Wh[4*c+2] = v.z; Wh[4*c+3] = v.w;
        }
    }
    float Wi[18];
    {
        const float2* p = reinterpret_cast<const float2*>(&swi[j * 18]);
        #pragma unroll
        for (int c = 0; c < 9; c++) { float2 v = p[c]; Wi[2*c] = v.x; Wi[2*c+1] = v.y; }
    }
    const float bj = bih2[j] + bhh2[j];

    float z = bj;
    {
        const float2* yp = reinterpret_cast<const float2*>(g_y + (size_t)b * 18);
        #pragma unroll
        for (int c = 0; c < 9; c++) {
            float2 v = yp[c];
            z = fmaf(Wi[2*c], v.x, z);
            z = fmaf(Wi[2*c+1], v.y, z);
        }
    }
    float h = ftanh(z);
    hs[wIn][0][j] = h;

    for (int t = 1; t < OUTLEN; t++) {
        __syncwarp();
        const float4* hp = reinterpret_cast<const float4*>(&hs[wIn][t - 1][0]);
        float a0 = bj, a1 = 0.f, a2 = 0.f, a3 = 0.f;
        #pragma unroll
        for (int c = 0; c < 8; c += 4) {
            float4 v0 = hp[c],     v1 = hp[c + 1];
            float4 v2 = hp[c + 2], v3 = hp[c + 3];
            a0 = fmaf(Wh[4*c+0],  v0.x, a0); a0 = fmaf(Wh[4*c+1],  v0.y, a0);
            a1 = fmaf(Wh[4*c+2],  v0.z, a1); a1 = fmaf(Wh[4*c+3],  v0.w, a1);
            a2 = fmaf(Wh[4*c+4],  v1.x, a2); a2 = fmaf(Wh[4*c+5],  v1.y, a2);
            a3 = fmaf(Wh[4*c+6],  v1.z, a3); a3 = fmaf(Wh[4*c+7],  v1.w, a3);
            a0 = fmaf(Wh[4*c+8],  v2.x, a0); a0 = fmaf(Wh[4*c+9],  v2.y, a0);
            a1 = fmaf(Wh[4*c+10], v2.z, a1); a1 = fmaf(Wh[4*c+11], v2.w, a1);
            a2 = fmaf(Wh[4*c+12], v3.x, a2); a2 = fmaf(Wh[4*c+13], v3.y, a2);
            a3 = fmaf(Wh[4*c+14], v3.z, a3); a3 = fmaf(Wh[4*c+15], v3.w, a3);
        }
        h = ftanh((a0 + a1) + (a2 + a3));
        hs[wIn][t][j] = h;
    }
    __syncwarp();

    float* op = out + (size_t)b * (OUTLEN * 3);
    for (int p = j; p < OUTLEN * 3; p += 32) {
        const int t = p / 3, o = p - 3 * t;
        const float4* yr = reinterpret_cast<const float4*>(&hs[wIn][t][0]);
        const float4* wr = reinterpret_cast<const float4*>(&swo[o * 32]);
        float acc = bout[o];
        #pragma unroll
        for (int c = 0; c < 8; c++) {
            float4 yv = yr[c], wv = wr[c];
            acc = fmaf(yv.x, wv.x, acc);
            acc = fmaf(yv.y, wv.y, acc);
            acc = fmaf(yv.z, wv.z, acc);
            acc = fmaf(yv.w, wv.w, acc);
        }
        op[p] = acc;
    }
}

// ---------------------------------------------------------------------------
// Launch pattern [rnn1, rnn2, dummy]: the harness pre-issues 2 launches, and
// ncu (-s 5 -c 1) captures our 4th launch = rnn1 of call 2 -> next profile
// finally shows the dominant kernel.
// ---------------------------------------------------------------------------
extern "C" void kernel_launch(void* const* d_in, const int* in_sizes, int n_in,
                              void* d_out, int out_size)
{
    const float* x     = (const float*)d_in[0];
    const float* wih_f = (const float*)d_in[1];
    const float* whh_f = (const float*)d_in[2];
    const float* bih_f = (const float*)d_in[3];
    const float* bhh_f = (const float*)d_in[4];
    const float* wih_b = (const float*)d_in[5];
    const float* whh_b = (const float*)d_in[6];
    const float* bih_b = (const float*)d_in[7];
    const float* bhh_b = (const float*)d_in[8];
    const float* wih2  = (const float*)d_in[9];
    const float* whh2  = (const float*)d_in[10];
    const float* bih2  = (const float*)d_in[11];
    const float* bhh2  = (const float*)d_in[12];
    const float* wout  = (const float*)d_in[13];
    const float* bout  = (const float*)d_in[14];
    float* out = (float*)d_out;

    rnn1_kernel<<<205, 128>>>(x, wih_f, whh_f, bih_f, bhh_f,
                              wih_b, whh_b, bih_b, bhh_b);
    rnn2_kernel<<<512, 256>>>(wih2, whh2, bih2, bhh2, wout, bout, out);
    dummy_kernel<<<1, 32>>>();
}

// round 8
// speedup vs baseline: 1.3421x; 1.3421x over previous
#include <cuda_runtime.h>
typedef unsigned long long u64;

#define TT 2048
#define BB 4096
#define OUTLEN 25
#define TPW 20             // tasks (batches) per warp: 10 pairs x 2 packed
#define WPD 205            // warps per direction
#define NWIN (TT/8)        // 256 windows of 8 steps

__device__ float g_y[BB * 18];

__device__ __forceinline__ u64 pack2(float lo, float hi) {
    u64 d; asm("mov.b64 %0,{%1,%2};" : "=l"(d) : "f"(lo), "f"(hi)); return d;
}
__device__ __forceinline__ void unpack2(u64 v, float& lo, float& hi) {
    asm("mov.b64 {%0,%1},%2;" : "=f"(lo), "=f"(hi) : "l"(v));
}
__device__ __forceinline__ u64 fma2(u64 a, u64 b, u64 c) {
    u64 d; asm("fma.rn.f32x2 %0,%1,%2,%3;" : "=l"(d) : "l"(a), "l"(b), "l"(c)); return d;
}
__device__ __forceinline__ u64 mul2(u64 a, u64 b) {
    u64 d; asm("mul.rn.f32x2 %0,%1,%2;" : "=l"(d) : "l"(a), "l"(b)); return d;
}
__device__ __forceinline__ u64 add2(u64 a, u64 b) {
    u64 d; asm("add.rn.f32x2 %0,%1,%2;" : "=l"(d) : "l"(a), "l"(b)); return d;
}
__device__ __forceinline__ float tanha(float x) {
    float y; asm("tanh.approx.f32 %0,%1;" : "=f"(y) : "f"(x)); return y;
}
__device__ __forceinline__ float ftanh(float x) {
    x = fminf(fmaxf(x, -9.0f), 9.0f);
    float e = __expf(2.0f * x);
    return __fdividef(e - 1.0f, e + 1.0f);
}

__global__ void dummy_kernel() {}

// ---------------------------------------------------------------------------
// Stage 1: bidirectional Elman RNN H1=9 over T=2048, f32x2-packed.
// Warp = 10 lane-triples x 2 batches (lo/hi of f32x2) = 20 tasks.
// Lane r of a triple owns units 3r..3r+2 of BOTH batches (weights packed
// (w,w)). 103 CTAs x 4 warps -> exactly 1 warp/SMSP, no stragglers.
// x staged via cp.async into per-warp smem (8-step windows, double buffer);
// x-projection zx precomputed in 4-step bulks (off the recurrent chain).
// tanh.approx except the last 32 steps (precise tail; contraction kills the
// approx error - verified in R0/R5/R6: rel_err stayed 1.7e-7).
// R7 bug fixed: window byte offset is t0 * 20 bytes (5 floats/step), not 80.
// ---------------------------------------------------------------------------
__global__ __launch_bounds__(128, 1) void rnn1_kernel(
    const float* __restrict__ x,
    const float* __restrict__ wih_f, const float* __restrict__ whh_f,
    const float* __restrict__ bih_f, const float* __restrict__ bhh_f,
    const float* __restrict__ wih_b, const float* __restrict__ whh_b,
    const float* __restrict__ bih_b, const float* __restrict__ bhh_b)
{
    // [warp][buf][pair*21 + (A:0..9 | B:10..19) float4 chunks], pad 1/pair
    __shared__ float4 sx4[4][2][210];

    const int wIn  = threadIdx.x >> 5;
    const int lane = threadIdx.x & 31;
    const int wid  = blockIdx.x * 4 + wIn;
    if (wid >= 2 * WPD) return;

    const bool bwd = (wid >= WPD);
    const int  wg  = bwd ? wid - WPD : wid;
    const int  tri = min(lane / 3, 9);     // lanes 30,31 shadow pair 9
    const int  r   = lane % 3;
    const int  rA  = (r + 1) % 3, rB = (r + 2) % 3;
    const int  laneA = 3 * tri + rA, laneB = 3 * tri + rB;

    const float* wih = bwd ? wih_b : wih_f;
    const float* whh = bwd ? whh_b : whh_f;
    const float* bih = bwd ? bih_b : bih_f;
    const float* bhh = bwd ? bhh_b : bhh_f;

    // packed weights: same value in both halves (both batches share dir)
    u64 WX[3][5], WhO[3][3], WhA[3][3], WhB[3][3], B2[3];
    #pragma unroll
    for (int m = 0; m < 3; m++) {
        const int j = 3 * r + m;
        #pragma unroll
        for (int k = 0; k < 5; k++) { float w = wih[j*5+k]; WX[m][k] = pack2(w, w); }
        #pragma unroll
        for (int i = 0; i < 3; i++) {
            float wo = whh[j*9 + 3*r  + i]; WhO[m][i] = pack2(wo, wo);
            float wa = whh[j*9 + 3*rA + i]; WhA[m][i] = pack2(wa, wa);
            float wb = whh[j*9 + 3*rB + i]; WhB[m][i] = pack2(wb, wb);
        }
        float bv = bih[j] + bhh[j];
        B2[m] = pack2(bv, bv);
    }

    // ---- cp.async loader: 200 float4 chunks/window (slot 0..19, c 0..9) --
    const char* xc = (const char*)x;
    u64      gsrc[7];
    unsigned sdst[7];
    {
        unsigned sbase = (unsigned)__cvta_generic_to_shared(&sx4[wIn][0][0]);
        #pragma unroll
        for (int k = 0; k < 7; k++) {
            int id = lane + 32 * k;
            int idc = min(id, 199);
            int slot = idc / 10, c = idc - 10 * slot;
            int b = min(wg * TPW + slot, BB - 1);
            gsrc[k] = (u64)(xc + (size_t)b * (TT * 20) + (size_t)c * 16);
            sdst[k] = sbase + ((slot >> 1) * 21 + (slot & 1) * 10 + c) * 16;
        }
    }
    // window byte offset: t0 steps x 5 floats x 4 bytes = t0 * 20 bytes
    #define CPA(g, bufoff) do {                                               \
        u64 wb = (u64)(bwd ? (TT - 8 - 8 * (g)) : (8 * (g))) * 20;            \
        _Pragma("unroll")                                                     \
        for (int k = 0; k < 7; k++)                                           \
            if (lane + 32 * k < 200)                                          \
                asm volatile("cp.async.cg.shared.global [%0], [%1], 16;\n"    \
                    :: "r"(sdst[k] + (bufoff)), "l"(gsrc[k] + wb));           \
        asm volatile("cp.async.commit_group;\n");                             \
    } while (0)
    const unsigned BUFB = 210 * 16;   // bytes per buffer

    u64 hP[3] = {0, 0, 0}, Ha[3] = {0, 0, 0}, Hb[3] = {0, 0, 0};
    u64 zxw[4][3];

    // bulk x-projection for a 4-step half-window (independent of h)
    #define ZXH(buf, half) do {                                               \
        const float4* s4 = &sx4[wIn][buf][tri * 21 + (half) * 5];             \
        float4 a0 = s4[0],  a1 = s4[1],  a2 = s4[2],  a3 = s4[3],  a4 = s4[4];\
        float4 c0 = s4[10], c1 = s4[11], c2 = s4[12], c3 = s4[13], c4 = s4[14];\
        float fa[20], fb[20];                                                 \
        fa[0]=a0.x; fa[1]=a0.y; fa[2]=a0.z; fa[3]=a0.w;                       \
        fa[4]=a1.x; fa[5]=a1.y; fa[6]=a1.z; fa[7]=a1.w;                       \
        fa[8]=a2.x; fa[9]=a2.y; fa[10]=a2.z; fa[11]=a2.w;                     \
        fa[12]=a3.x; fa[13]=a3.y; fa[14]=a3.z; fa[15]=a3.w;                   \
        fa[16]=a4.x; fa[17]=a4.y; fa[18]=a4.z; fa[19]=a4.w;                   \
        fb[0]=c0.x; fb[1]=c0.y; fb[2]=c0.z; fb[3]=c0.w;                       \
        fb[4]=c1.x; fb[5]=c1.y; fb[6]=c1.z; fb[7]=c1.w;                       \
        fb[8]=c2.x; fb[9]=c2.y; fb[10]=c2.z; fb[11]=c2.w;                     \
        fb[12]=c3.x; fb[13]=c3.y; fb[14]=c3.z; fb[15]=c3.w;                   \
        fb[16]=c4.x; fb[17]=c4.y; fb[18]=c4.z; fb[19]=c4.w;                   \
        _Pragma("unroll")                                                     \
        for (int q = 0; q < 4; q++) {                                         \
            u64 X0 = pack2(fa[q*5+0], fb[q*5+0]);                             \
            u64 X1 = pack2(fa[q*5+1], fb[q*5+1]);                             \
            u64 X2 = pack2(fa[q*5+2], fb[q*5+2]);                             \
            u64 X3 = pack2(fa[q*5+3], fb[q*5+3]);                             \
            u64 X4 = pack2(fa[q*5+4], fb[q*5+4]);                             \
            _Pragma("unroll")                                                 \
            for (int m = 0; m < 3; m++) {                                     \
                u64 z = fma2(WX[m][0], X0, B2[m]);                            \
                z = fma2(WX[m][1], X1, z); z = fma2(WX[m][2], X2, z);         \
                z = fma2(WX[m][3], X3, z); z = fma2(WX[m][4], X4, z);         \
                zxw[q][m] = z;                                                \
            }                                                                 \
        }                                                                     \
    } while (0)

    #define STEP(TANHF, q) do {                                               \
        u64 nh[3];                                                            \
        _Pragma("unroll")                                                     \
        for (int m = 0; m < 3; m++) {                                         \
            u64 t1 = fma2(WhO[m][2], hP[2], zxw[q][m]);                       \
            t1 = fma2(WhO[m][1], hP[1], t1);                                  \
            t1 = fma2(WhO[m][0], hP[0], t1);                                  \
            u64 t2 = mul2(WhA[m][0], Ha[0]);                                  \
            t2 = fma2(WhA[m][1], Ha[1], t2); t2 = fma2(WhA[m][2], Ha[2], t2); \
            u64 t3 = mul2(WhB[m][0], Hb[0]);                                  \
            t3 = fma2(WhB[m][1], Hb[1], t3); t3 = fma2(WhB[m][2], Hb[2], t3); \
            u64 z = add2(add2(t1, t2), t3);                                   \
            float sa, sb; unpack2(z, sa, sb);                                 \
            nh[m] = pack2(TANHF(sa), TANHF(sb));                              \
        }                                                                     \
        hP[0] = nh[0]; hP[1] = nh[1]; hP[2] = nh[2];                          \
        Ha[0] = __shfl_sync(0xffffffffu, hP[0], laneA);                       \
        Ha[1] = __shfl_sync(0xffffffffu, hP[1], laneA);                       \
        Ha[2] = __shfl_sync(0xffffffffu, hP[2], laneA);                       \
        Hb[0] = __shfl_sync(0xffffffffu, hP[0], laneB);                       \
        Hb[1] = __shfl_sync(0xffffffffu, hP[1], laneB);                       \
        Hb[2] = __shfl_sync(0xffffffffu, hP[2], laneB);                       \
    } while (0)

    #define CONS(TANHF, buf) do {                                             \
        if (!bwd) {                                                           \
            ZXH(buf, 0);                                                      \
            STEP(TANHF, 0); STEP(TANHF, 1); STEP(TANHF, 2); STEP(TANHF, 3);   \
            ZXH(buf, 1);                                                      \
            STEP(TANHF, 0); STEP(TANHF, 1); STEP(TANHF, 2); STEP(TANHF, 3);   \
        } else {                                                              \
            ZXH(buf, 1);                                                      \
            STEP(TANHF, 3); STEP(TANHF, 2); STEP(TANHF, 1); STEP(TANHF, 0);   \
            ZXH(buf, 0);                                                      \
            STEP(TANHF, 3); STEP(TANHF, 2); STEP(TANHF, 1); STEP(TANHF, 0);   \
        }                                                                     \
    } while (0)

    CPA(0, 0);
    CPA(1, BUFB);
    for (int g = 0; g < NWIN; g++) {
        asm volatile("cp.async.wait_group 1;\n");
        __syncwarp();
        const int buf = g & 1;
        if (g < NWIN - 4) CONS(tanha, buf);
        else              CONS(ftanh, buf);
        __syncwarp();
        if (g + 2 < NWIN) CPA(g + 2, buf ? BUFB : 0);
    }

    if (lane < 30) {
        const int dirOff = bwd ? 9 : 0;
        const int bA = wg * TPW + 2 * tri;
        const int bB = bA + 1;
        float a0, b0, a1, b1, a2, b2;
        unpack2(hP[0], a0, b0); unpack2(hP[1], a1, b1); unpack2(hP[2], a2, b2);
        if (bA < BB) {
            float* d = g_y + bA * 18 + dirOff + 3 * r;
            d[0] = a0; d[1] = a1; d[2] = a2;
        }
        if (bB < BB) {
            float* d = g_y + bB * 18 + dirOff + 3 * r;
            d[0] = b0; d[1] = b1; d[2] = b2;
        }
    }
    #undef CPA
    #undef ZXH
    #undef STEP
    #undef CONS
}

// ---------------------------------------------------------------------------
// Stage 2: H2=32 RNN, 25 steps + linear 32->3 (R4/R6 version, precise tanh:
// its errors feed the output directly, no contraction to hide behind).
// ---------------------------------------------------------------------------
__global__ __launch_bounds__(256) void rnn2_kernel(
    const float* __restrict__ wih2, const float* __restrict__ whh2,
    const float* __restrict__ bih2, const float* __restrict__ bhh2,
    const float* __restrict__ wout, const float* __restrict__ bout,
    float* __restrict__ out)
{
    __shared__ float swh[1024], swi[576], swo[96];
    __shared__ float hs[8][OUTLEN][32];

    const int tid = threadIdx.x;
    for (int i = tid; i < 1024; i += 256) swh[i] = whh2[i];
    for (int i = tid; i < 576;  i += 256) swi[i] = wih2[i];
    if (tid < 96) swo[tid] = wout[tid];
    __syncthreads();

    const int wIn = tid >> 5;
    const int j   = tid & 31;
    const int b   = blockIdx.x * 8 + wIn;

    float Wh[32];
    {
        const float4* p = reinterpret_cast<const float4*>(&swh[j * 32]);
        #pragma unroll
        for (int c = 0; c < 8; c++) {
            float4 v = p[c];
            Wh[4*c] = v.x; Wh[4*c+1] = v.y; Wh[4*c+2] = v.z; Wh[4*c+3] = v.w;
        }
    }
    float Wi[18];
    {
        const float2* p = reinterpret_cast<const float2*>(&swi[j * 18]);
        #pragma unroll
        for (int c = 0; c < 9; c++) { float2 v = p[c]; Wi[2*c] = v.x; Wi[2*c+1] = v.y; }
    }
    const float bj = bih2[j] + bhh2[j];

    float z = bj;
    {
        const float2* yp = reinterpret_cast<const float2*>(g_y + (size_t)b * 18);
        #pragma unroll
        for (int c = 0; c < 9; c++) {
            float2 v = yp[c];
            z = fmaf(Wi[2*c], v.x, z);
            z = fmaf(Wi[2*c+1], v.y, z);
        }
    }
    float h = ftanh(z);
    hs[wIn][0][j] = h;

    for (int t = 1; t < OUTLEN; t++) {
        __syncwarp();
        const float4* hp = reinterpret_cast<const float4*>(&hs[wIn][t - 1][0]);
        float a0 = bj, a1 = 0.f, a2 = 0.f, a3 = 0.f;
        #pragma unroll
        for (int c = 0; c < 8; c += 4) {
            float4 v0 = hp[c],     v1 = hp[c + 1];
            float4 v2 = hp[c + 2], v3 = hp[c + 3];
            a0 = fmaf(Wh[4*c+0],  v0.x, a0); a0 = fmaf(Wh[4*c+1],  v0.y, a0);
            a1 = fmaf(Wh[4*c+2],  v0.z, a1); a1 = fmaf(Wh[4*c+3],  v0.w, a1);
            a2 = fmaf(Wh[4*c+4],  v1.x, a2); a2 = fmaf(Wh[4*c+5],  v1.y, a2);
            a3 = fmaf(Wh[4*c+6],  v1.z, a3); a3 = fmaf(Wh[4*c+7],  v1.w, a3);
            a0 = fmaf(Wh[4*c+8],  v2.x, a0); a0 = fmaf(Wh[4*c+9],  v2.y, a0);
            a1 = fmaf(Wh[4*c+10], v2.z, a1); a1 = fmaf(Wh[4*c+11], v2.w, a1);
            a2 = fmaf(Wh[4*c+12], v3.x, a2); a2 = fmaf(Wh[4*c+13], v3.y, a2);
            a3 = fmaf(Wh[4*c+14], v3.z, a3); a3 = fmaf(Wh[4*c+15], v3.w, a3);
        }
        h = ftanh((a0 + a1) + (a2 + a3));
        hs[wIn][t][j] = h;
    }
    __syncwarp();

    float* op = out + (size_t)b * (OUTLEN * 3);
    for (int p = j; p < OUTLEN * 3; p += 32) {
        const int t = p / 3, o = p - 3 * t;
        const float4* yr = reinterpret_cast<const float4*>(&hs[wIn][t][0]);
        const float4* wr = reinterpret_cast<const float4*>(&swo[o * 32]);
        float acc = bout[o];
        #pragma unroll
        for (int c = 0; c < 8; c++) {
            float4 yv = yr[c], wv = wr[c];
            acc = fmaf(yv.x, wv.x, acc);
            acc = fmaf(yv.y, wv.y, acc);
            acc = fmaf(yv.z, wv.z, acc);
            acc = fmaf(yv.w, wv.w, acc);
        }
        op[p] = acc;
    }
}

// ---------------------------------------------------------------------------
// Launch pattern [rnn1, rnn2, dummy] kept: ncu capture stays on rnn1.
// ---------------------------------------------------------------------------
extern "C" void kernel_launch(void* const* d_in, const int* in_sizes, int n_in,
                              void* d_out, int out_size)
{
    const float* x     = (const float*)d_in[0];
    const float* wih_f = (const float*)d_in[1];
    const float* whh_f = (const float*)d_in[2];
    const float* bih_f = (const float*)d_in[3];
    const float* bhh_f = (const float*)d_in[4];
    const float* wih_b = (const float*)d_in[5];
    const float* whh_b = (const float*)d_in[6];
    const float* bih_b = (const float*)d_in[7];
    const float* bhh_b = (const float*)d_in[8];
    const float* wih2  = (const float*)d_in[9];
    const float* whh2  = (const float*)d_in[10];
    const float* bih2  = (const float*)d_in[11];
    const float* bhh2  = (const float*)d_in[12];
    const float* wout  = (const float*)d_in[13];
    const float* bout  = (const float*)d_in[14];
    float* out = (float*)d_out;

    // 103 CTAs x 4 warps = 412 warps (410 active), 1 CTA/SM, 1 warp/SMSP
    rnn1_kernel<<<103, 128>>>(x, wih_f, whh_f, bih_f, bhh_f,
                              wih_b, whh_b, bih_b, bhh_b);
    rnn2_kernel<<<512, 256>>>(wih2, whh2, bih2, bhh2, wout, bout, out);
    dummy_kernel<<<1, 32>>>();
}